// round 3
// baseline (speedup 1.0000x reference)
#include <cuda_runtime.h>

#define N_NODES 50000
#define N_EDGES 1600000
#define HID 64
#define WSTRIDE 76            // padded row stride (floats): conflict-free LDS.128
#define FULL 0xffffffffu

// ---------------- scratch (device globals; no allocation allowed) -------------
__device__ int   g_deg[N_NODES];
__device__ int   g_cursor[N_NODES];
__device__ int   g_rowstart[N_NODES + 1];
__device__ int   g_ssrc[N_EDGES];
__device__ float g_z0[N_NODES];
__device__ float g_z[N_NODES * HID];
__device__ float g_y[N_NODES * HID];
__device__ float g_stats[2 * HID];
__device__ float g_scale[HID];
__device__ float g_shift[HID];

// ---------------- CSR build ---------------------------------------------------
__global__ void k_zero() {
    int i = blockIdx.x * blockDim.x + threadIdx.x;
    if (i < N_NODES) { g_deg[i] = 0; g_cursor[i] = 0; }
    if (i < 2 * HID) g_stats[i] = 0.f;
}

__global__ void k_hist(const int* __restrict__ dst) {
    int e = blockIdx.x * blockDim.x + threadIdx.x;
    if (e < N_EDGES) atomicAdd(&g_deg[dst[e]], 1);
}

__global__ void k_scan() {
    __shared__ int part[1024];
    const int CH = (N_NODES + 1023) / 1024;   // 49
    int tid = threadIdx.x;
    int base = tid * CH;
    int s = 0;
    for (int j = 0; j < CH; j++) {
        int idx = base + j;
        if (idx < N_NODES) s += g_deg[idx];
    }
    part[tid] = s;
    __syncthreads();
    for (int off = 1; off < 1024; off <<= 1) {
        int v = (tid >= off) ? part[tid - off] : 0;
        __syncthreads();
        if (tid >= off) part[tid] += v;
        __syncthreads();
    }
    int run = (tid > 0) ? part[tid - 1] : 0;
    for (int j = 0; j < CH; j++) {
        int idx = base + j;
        if (idx < N_NODES) { g_rowstart[idx] = run; run += g_deg[idx]; }
    }
    if (tid == 1023) g_rowstart[N_NODES] = part[1023];
}

__global__ void k_permute(const int* __restrict__ src, const int* __restrict__ dst) {
    int e = blockIdx.x * blockDim.x + threadIdx.x;
    if (e < N_EDGES) {
        int d = dst[e];
        int p = g_rowstart[d] + atomicAdd(&g_cursor[d], 1);
        g_ssrc[p] = src[e];
    }
}

// ---------------- layer 1 aggregation (scalar features) ----------------------
__global__ void k_agg1(const float* __restrict__ x, const float* __restrict__ eps) {
    int gw = (blockIdx.x * blockDim.x + threadIdx.x) >> 5;
    if (gw >= N_NODES) return;
    int lane = threadIdx.x & 31;
    int beg = g_rowstart[gw], end = g_rowstart[gw + 1];
    float s = 0.f;
    for (int e = beg + lane; e < end; e += 32) s += x[g_ssrc[e]];
#pragma unroll
    for (int off = 16; off; off >>= 1) s += __shfl_down_sync(FULL, s, off);
    if (lane == 0) g_z0[gw] = fmaf(1.f + eps[0], x[gw], s);
}

// ---------------- aggregation for 64-dim layers, BN folded in ----------------
// z[i][f] = sc[f]*((1+eps)*y[i][f] + sum_j y[j][f]) + sh[f]*((1+eps)+deg)
__global__ void k_agg(const float* __restrict__ eps, int layer) {
    int gw = (blockIdx.x * blockDim.x + threadIdx.x) >> 5;
    if (gw >= N_NODES) return;
    int lane = threadIdx.x & 31;
    int beg = g_rowstart[gw], end = g_rowstart[gw + 1];
    const float2* Y = (const float2*)g_y;
    float2 a0 = make_float2(0.f, 0.f), a1 = make_float2(0.f, 0.f);
    for (int e0 = beg; e0 < end; e0 += 32) {
        int cnt = min(32, end - e0);
        int s = (lane < cnt) ? g_ssrc[e0 + lane] : 0;
        int j = 0;
        for (; j + 2 <= cnt; j += 2) {
            int s0 = __shfl_sync(FULL, s, j);
            int s1 = __shfl_sync(FULL, s, j + 1);
            float2 v0 = Y[s0 * 32 + lane];
            float2 v1 = Y[s1 * 32 + lane];
            a0.x += v0.x; a0.y += v0.y;
            a1.x += v1.x; a1.y += v1.y;
        }
        if (j < cnt) {
            int s0 = __shfl_sync(FULL, s, j);
            float2 v0 = Y[s0 * 32 + lane];
            a0.x += v0.x; a0.y += v0.y;
        }
    }
    float ep = 1.f + eps[layer];
    float2 sc = ((const float2*)g_scale)[lane];
    float2 sh = ((const float2*)g_shift)[lane];
    float2 ys = Y[gw * 32 + lane];
    float dg = ep + (float)(end - beg);
    float2 z;
    z.x = sc.x * fmaf(ep, ys.x, a0.x + a1.x) + sh.x * dg;
    z.y = sc.y * fmaf(ep, ys.y, a0.y + a1.y) + sh.y * dg;
    ((float2*)g_z)[gw * 32 + lane] = z;
}

// ---------------- MLP: y = relu(relu(z@W1+b1)@W2+b2), accumulate BN stats ----
__global__ void __launch_bounds__(256) k_mlp(
    const float* __restrict__ W1, const float* __restrict__ b1,
    const float* __restrict__ W2, const float* __restrict__ b2)
{
    __shared__ float w1t[HID * WSTRIDE];
    __shared__ float w2t[HID * WSTRIDE];
    __shared__ float zsh[4][HID];
    __shared__ float tsh[4][HID];
    __shared__ float red[2][256];

    int tid = threadIdx.x;
    for (int idx = tid; idx < HID * HID; idx += 256) {
        int k = idx >> 6, o = idx & 63;
        w1t[o * WSTRIDE + k] = W1[idx];
        w2t[o * WSTRIDE + k] = W2[idx];
    }
    int o = tid & 63, n = tid >> 6;
    float b1o = b1[o], b2o = b2[o];
    __syncthreads();

    float ssum = 0.f, ssq = 0.f;
    const int ngroups = N_NODES / 4;
    for (int g = blockIdx.x; g < ngroups; g += gridDim.x) {
        int node0 = g * 4;
        zsh[n][o] = g_z[node0 * HID + tid];
        __syncthreads();
        float acc = b1o;
        {
            const float4* zp = (const float4*)zsh[n];
            const float4* wp = (const float4*)(w1t + o * WSTRIDE);
#pragma unroll
            for (int k = 0; k < HID / 4; k++) {
                float4 a = zp[k], w = wp[k];
                acc = fmaf(a.x, w.x, acc); acc = fmaf(a.y, w.y, acc);
                acc = fmaf(a.z, w.z, acc); acc = fmaf(a.w, w.w, acc);
            }
        }
        tsh[n][o] = fmaxf(acc, 0.f);
        __syncthreads();
        acc = b2o;
        {
            const float4* tp = (const float4*)tsh[n];
            const float4* wp = (const float4*)(w2t + o * WSTRIDE);
#pragma unroll
            for (int k = 0; k < HID / 4; k++) {
                float4 a = tp[k], w = wp[k];
                acc = fmaf(a.x, w.x, acc); acc = fmaf(a.y, w.y, acc);
                acc = fmaf(a.z, w.z, acc); acc = fmaf(a.w, w.w, acc);
            }
        }
        float yv = fmaxf(acc, 0.f);
        g_y[node0 * HID + tid] = yv;
        ssum += yv; ssq += yv * yv;
        __syncthreads();
    }
    red[0][tid] = ssum; red[1][tid] = ssq;
    __syncthreads();
    if (tid < HID) {
        float a = red[0][tid] + red[0][tid + 64] + red[0][tid + 128] + red[0][tid + 192];
        float q = red[1][tid] + red[1][tid + 64] + red[1][tid + 128] + red[1][tid + 192];
        atomicAdd(&g_stats[tid], a);
        atomicAdd(&g_stats[HID + tid], q);
    }
}

// ---------------- MLP for layer 1 (scalar -> 64 -> 64) ------------------------
__global__ void __launch_bounds__(256) k_mlp1(
    const float* __restrict__ w1a, const float* __restrict__ b1a,
    const float* __restrict__ W2, const float* __restrict__ b2)
{
    __shared__ float w2t[HID * WSTRIDE];
    __shared__ float zs[4];
    __shared__ float tsh[4][HID];
    __shared__ float red[2][256];

    int tid = threadIdx.x;
    for (int idx = tid; idx < HID * HID; idx += 256)
        w2t[(idx & 63) * WSTRIDE + (idx >> 6)] = W2[idx];
    int o = tid & 63, n = tid >> 6;
    float w1o = w1a[o], b1o = b1a[o], b2o = b2[o];
    __syncthreads();

    float ssum = 0.f, ssq = 0.f;
    const int ngroups = N_NODES / 4;
    for (int g = blockIdx.x; g < ngroups; g += gridDim.x) {
        int node0 = g * 4;
        if (tid < 4) zs[tid] = g_z0[node0 + tid];
        __syncthreads();
        tsh[n][o] = fmaxf(fmaf(zs[n], w1o, b1o), 0.f);
        __syncthreads();
        float acc = b2o;
        {
            const float4* tp = (const float4*)tsh[n];
            const float4* wp = (const float4*)(w2t + o * WSTRIDE);
#pragma unroll
            for (int k = 0; k < HID / 4; k++) {
                float4 a = tp[k], w = wp[k];
                acc = fmaf(a.x, w.x, acc); acc = fmaf(a.y, w.y, acc);
                acc = fmaf(a.z, w.z, acc); acc = fmaf(a.w, w.w, acc);
            }
        }
        float yv = fmaxf(acc, 0.f);
        g_y[node0 * HID + tid] = yv;
        ssum += yv; ssq += yv * yv;
        __syncthreads();
    }
    red[0][tid] = ssum; red[1][tid] = ssq;
    __syncthreads();
    if (tid < HID) {
        float a = red[0][tid] + red[0][tid + 64] + red[0][tid + 128] + red[0][tid + 192];
        float q = red[1][tid] + red[1][tid + 64] + red[1][tid + 128] + red[1][tid + 192];
        atomicAdd(&g_stats[tid], a);
        atomicAdd(&g_stats[HID + tid], q);
    }
}

// ---------------- BN stats -> affine (scale/shift), reset stats ---------------
__global__ void k_bn(const float* __restrict__ gamma, const float* __restrict__ beta) {
    int f = threadIdx.x;
    if (f < HID) {
        float s = g_stats[f], q = g_stats[HID + f];
        const float inv = 1.f / (float)N_NODES;
        float mu = s * inv;
        float var = q * inv - mu * mu;
        float rstd = rsqrtf(var + 1e-5f);
        float sc = gamma[f] * rstd;
        g_scale[f] = sc;
        g_shift[f] = beta[f] - mu * sc;
        g_stats[f] = 0.f;
        g_stats[HID + f] = 0.f;
    }
}

// ---------------- final: out = (y*sc+sh) @ fc_w + fc_b ------------------------
__global__ void k_fc(const float* __restrict__ fcw, const float* __restrict__ fcb,
                     float* __restrict__ out) {
    int gw = (blockIdx.x * blockDim.x + threadIdx.x) >> 5;
    if (gw >= N_NODES) return;
    int lane = threadIdx.x & 31;
    float2 y  = ((const float2*)g_y)[gw * 32 + lane];
    float2 sc = ((const float2*)g_scale)[lane];
    float2 sh = ((const float2*)g_shift)[lane];
    float2 fw = ((const float2*)fcw)[lane];
    float p = fmaf(fmaf(y.x, sc.x, sh.x), fw.x,
                   fmaf(y.y, sc.y, sh.y) * fw.y);
#pragma unroll
    for (int off = 16; off; off >>= 1) p += __shfl_down_sync(FULL, p, off);
    if (lane == 0) out[gw] = p + fcb[0];
}

// ---------------- launch ------------------------------------------------------
extern "C" void kernel_launch(void* const* d_in, const int* in_sizes, int n_in,
                              void* d_out, int out_size) {
    const float* x      = (const float*)d_in[0];
    const int*   ei     = (const int*)  d_in[1];
    const int*   src    = ei;
    const int*   dst    = ei + N_EDGES;
    const float* w1a    = (const float*)d_in[2];
    const float* b1a    = (const float*)d_in[3];
    const float* w2a    = (const float*)d_in[4];
    const float* b2a    = (const float*)d_in[5];
    const float* w1s    = (const float*)d_in[6];
    const float* b1s    = (const float*)d_in[7];
    const float* w2s    = (const float*)d_in[8];
    const float* b2s    = (const float*)d_in[9];
    const float* eps    = (const float*)d_in[10];
    const float* gammas = (const float*)d_in[11];
    const float* betas  = (const float*)d_in[12];
    const float* fcw    = (const float*)d_in[13];
    const float* fcb    = (const float*)d_in[14];
    float* out = (float*)d_out;

    const int EB = (N_EDGES + 255) / 256;          // 6250
    const int WB = (N_NODES * 32 + 255) / 256;     // 6250 (warp per node)
    const int MLP_GRID = 740;

    // CSR build (every replay; all scratch state re-derived)
    k_zero<<<(N_NODES + 255) / 256, 256>>>();
    k_hist<<<EB, 256>>>(dst);
    k_scan<<<1, 1024>>>();
    k_permute<<<EB, 256>>>(src, dst);

    // layer 1 (scalar input)
    k_agg1<<<WB, 256>>>(x, eps);
    k_mlp1<<<MLP_GRID, 256>>>(w1a, b1a, w2a, b2a);
    k_bn<<<1, 64>>>(gammas, betas);

    // layers 2-4
    for (int l = 0; l < 3; l++) {
        k_agg<<<WB, 256>>>(eps, l + 1);
        k_mlp<<<MLP_GRID, 256>>>(w1s + l * HID * HID, b1s + l * HID,
                                 w2s + l * HID * HID, b2s + l * HID);
        k_bn<<<1, 64>>>(gammas + (l + 1) * HID, betas + (l + 1) * HID);
    }

    // final FC with BN folded
    k_fc<<<WB, 256>>>(fcw, fcb, out);
}

// round 5
// speedup vs baseline: 1.2800x; 1.2800x over previous
#include <cuda_runtime.h>

#define N_NODES 50000
#define N_EDGES 1600000
#define HID 64
#define FULL 0xffffffffu

// ---------------- scratch (device globals; no allocation allowed) -------------
__device__ int   g_deg[N_NODES];
__device__ int   g_cursor[N_NODES];          // running write cursor (starts at rowstart)
__device__ int   g_rowstart[N_NODES + 1];
__device__ int   g_ssrc[N_EDGES];
__device__ float g_z0[N_NODES];
__device__ float g_z[N_NODES * HID];
__device__ float g_y[N_NODES * HID];
__device__ float g_stats[2 * HID];
__device__ float g_scale[HID];
__device__ float g_shift[HID];

// ---------------- CSR build ---------------------------------------------------
__global__ void k_zero() {
    int i = blockIdx.x * blockDim.x + threadIdx.x;
    if (i < N_NODES) g_deg[i] = 0;
    if (i < 2 * HID) g_stats[i] = 0.f;
}

__global__ void k_hist(const int* __restrict__ dst) {
    int e4 = blockIdx.x * blockDim.x + threadIdx.x;
    if (e4 < N_EDGES / 4) {
        int4 d = ((const int4*)dst)[e4];
        atomicAdd(&g_deg[d.x], 1);
        atomicAdd(&g_deg[d.y], 1);
        atomicAdd(&g_deg[d.z], 1);
        atomicAdd(&g_deg[d.w], 1);
    }
}

__global__ void k_scan() {
    __shared__ int part[1024];
    const int CH = (N_NODES + 1023) / 1024;   // 49
    int tid = threadIdx.x;
    int base = tid * CH;
    int s = 0;
    for (int j = 0; j < CH; j++) {
        int idx = base + j;
        if (idx < N_NODES) s += g_deg[idx];
    }
    part[tid] = s;
    __syncthreads();
    for (int off = 1; off < 1024; off <<= 1) {
        int v = (tid >= off) ? part[tid - off] : 0;
        __syncthreads();
        if (tid >= off) part[tid] += v;
        __syncthreads();
    }
    int run = (tid > 0) ? part[tid - 1] : 0;
    for (int j = 0; j < CH; j++) {
        int idx = base + j;
        if (idx < N_NODES) {
            g_rowstart[idx] = run;
            g_cursor[idx]   = run;   // cursor pre-seeded: permute atomicAdds directly
            run += g_deg[idx];
        }
    }
    if (tid == 1023) g_rowstart[N_NODES] = part[1023];
}

__global__ void k_permute(const int* __restrict__ src, const int* __restrict__ dst) {
    int e4 = blockIdx.x * blockDim.x + threadIdx.x;
    if (e4 < N_EDGES / 4) {
        int4 d = ((const int4*)dst)[e4];
        int4 s = ((const int4*)src)[e4];
        g_ssrc[atomicAdd(&g_cursor[d.x], 1)] = s.x;
        g_ssrc[atomicAdd(&g_cursor[d.y], 1)] = s.y;
        g_ssrc[atomicAdd(&g_cursor[d.z], 1)] = s.z;
        g_ssrc[atomicAdd(&g_cursor[d.w], 1)] = s.w;
    }
}

// ---------------- layer 1 aggregation (scalar features) ----------------------
__global__ void k_agg1(const float* __restrict__ x, const float* __restrict__ eps) {
    int gw = (blockIdx.x * blockDim.x + threadIdx.x) >> 5;
    if (gw >= N_NODES) return;
    int lane = threadIdx.x & 31;
    int beg = g_rowstart[gw], end = g_rowstart[gw + 1];
    float s = 0.f;
    for (int e = beg + lane; e < end; e += 32) s += x[g_ssrc[e]];
#pragma unroll
    for (int off = 16; off; off >>= 1) s += __shfl_down_sync(FULL, s, off);
    if (lane == 0) g_z0[gw] = fmaf(1.f + eps[0], x[gw], s);
}

// ---------------- aggregation for 64-dim layers, BN folded in ----------------
// float4 per lane, 16 lanes per row, 2 rows per LDG round.
// z[i][f] = sc[f]*((1+eps)*y[i][f] + sum_j y[j][f]) + sh[f]*((1+eps)+deg)
__global__ void k_agg(const float* __restrict__ eps, int layer) {
    int gw = (blockIdx.x * blockDim.x + threadIdx.x) >> 5;
    if (gw >= N_NODES) return;
    int lane = threadIdx.x & 31;
    int half = lane >> 4;            // 0 or 1: which of the 2 edges this lane serves
    int lq   = lane & 15;            // float4 slot within the row
    int beg = g_rowstart[gw], end = g_rowstart[gw + 1];
    const float4* __restrict__ Y4 = (const float4*)g_y;

    float4 a = make_float4(0.f, 0.f, 0.f, 0.f);
    for (int e0 = beg; e0 < end; e0 += 32) {
        int cnt = min(32, end - e0);
        int s = (lane < cnt) ? g_ssrc[e0 + lane] : 0;
        if (cnt == 32) {
#pragma unroll
            for (int j = 0; j < 32; j += 2) {
                int sj = __shfl_sync(FULL, s, j + half);
                float4 v = Y4[sj * 16 + lq];
                a.x += v.x; a.y += v.y; a.z += v.z; a.w += v.w;
            }
        } else {
            for (int j = 0; j < cnt; j += 2) {
                int e = j + half;
                int sj = __shfl_sync(FULL, s, e & 31);
                if (e < cnt) {
                    float4 v = Y4[sj * 16 + lq];
                    a.x += v.x; a.y += v.y; a.z += v.z; a.w += v.w;
                }
            }
        }
    }
    // combine the two half-warp partials (same features, complementary edges)
    a.x += __shfl_xor_sync(FULL, a.x, 16);
    a.y += __shfl_xor_sync(FULL, a.y, 16);
    a.z += __shfl_xor_sync(FULL, a.z, 16);
    a.w += __shfl_xor_sync(FULL, a.w, 16);

    if (half == 0) {
        float ep = 1.f + eps[layer];
        float4 sc = ((const float4*)g_scale)[lq];
        float4 sh = ((const float4*)g_shift)[lq];
        float4 ys = Y4[gw * 16 + lq];
        float dg = ep + (float)(end - beg);
        float4 z;
        z.x = sc.x * fmaf(ep, ys.x, a.x) + sh.x * dg;
        z.y = sc.y * fmaf(ep, ys.y, a.y) + sh.y * dg;
        z.z = sc.z * fmaf(ep, ys.z, a.z) + sh.z * dg;
        z.w = sc.w * fmaf(ep, ys.w, a.w) + sh.w * dg;
        ((float4*)g_z)[gw * 16 + lq] = z;
    }
}

// ---------------- MLP: register-resident weights, broadcast activations ------
// 128 threads = 2 subgroups x 64 output-threads; 8 nodes per iteration.
// Thread o holds W1[:,o] and W2[:,o] in registers; activations broadcast via LDS.
#define MLP_NPB 8   // nodes per block-iteration
__global__ void __launch_bounds__(128, 3) k_mlp(
    const float* __restrict__ W1, const float* __restrict__ b1,
    const float* __restrict__ W2, const float* __restrict__ b2)
{
    __shared__ float zsh[MLP_NPB * HID];
    __shared__ float tsh[MLP_NPB * HID];
    __shared__ float red[2][128];

    int tid = threadIdx.x;
    int o = tid & 63, sg = tid >> 6;

    float w1r[HID], w2r[HID];
#pragma unroll
    for (int k = 0; k < HID; k++) w1r[k] = W1[k * HID + o];
#pragma unroll
    for (int k = 0; k < HID; k++) w2r[k] = W2[k * HID + o];
    float b1o = b1[o], b2o = b2[o];

    const float4* zsh4 = (const float4*)zsh;
    const float4* tsh4 = (const float4*)tsh;

    float ssum = 0.f, ssq = 0.f;
    const int ngroups = N_NODES / MLP_NPB;     // 6250
    for (int g = blockIdx.x; g < ngroups; g += gridDim.x) {
        int node0 = g * MLP_NPB;
        // stage 8 node rows (512 floats) : one float4 per thread, coalesced
        ((float4*)zsh)[tid] = ((const float4*)(g_z + node0 * HID))[tid];
        __syncthreads();

        // layer 1: 4 nodes per thread (sg picks which 4)
        float ac0 = b1o, ac1 = b1o, ac2 = b1o, ac3 = b1o;
        {
            int r0 = (sg * 4 + 0) * 16, r1 = (sg * 4 + 1) * 16;
            int r2 = (sg * 4 + 2) * 16, r3 = (sg * 4 + 3) * 16;
#pragma unroll
            for (int k4 = 0; k4 < 16; k4++) {
                float4 z0 = zsh4[r0 + k4];   // broadcast across warp
                float4 z1 = zsh4[r1 + k4];
                float4 z2 = zsh4[r2 + k4];
                float4 z3 = zsh4[r3 + k4];
                float wa = w1r[4 * k4], wb = w1r[4 * k4 + 1];
                float wc = w1r[4 * k4 + 2], wd = w1r[4 * k4 + 3];
                ac0 = fmaf(z0.x, wa, ac0); ac1 = fmaf(z1.x, wa, ac1);
                ac2 = fmaf(z2.x, wa, ac2); ac3 = fmaf(z3.x, wa, ac3);
                ac0 = fmaf(z0.y, wb, ac0); ac1 = fmaf(z1.y, wb, ac1);
                ac2 = fmaf(z2.y, wb, ac2); ac3 = fmaf(z3.y, wb, ac3);
                ac0 = fmaf(z0.z, wc, ac0); ac1 = fmaf(z1.z, wc, ac1);
                ac2 = fmaf(z2.z, wc, ac2); ac3 = fmaf(z3.z, wc, ac3);
                ac0 = fmaf(z0.w, wd, ac0); ac1 = fmaf(z1.w, wd, ac1);
                ac2 = fmaf(z2.w, wd, ac2); ac3 = fmaf(z3.w, wd, ac3);
            }
        }
        tsh[(sg * 4 + 0) * HID + o] = fmaxf(ac0, 0.f);
        tsh[(sg * 4 + 1) * HID + o] = fmaxf(ac1, 0.f);
        tsh[(sg * 4 + 2) * HID + o] = fmaxf(ac2, 0.f);
        tsh[(sg * 4 + 3) * HID + o] = fmaxf(ac3, 0.f);
        __syncthreads();

        // layer 2
        ac0 = b2o; ac1 = b2o; ac2 = b2o; ac3 = b2o;
        {
            int r0 = (sg * 4 + 0) * 16, r1 = (sg * 4 + 1) * 16;
            int r2 = (sg * 4 + 2) * 16, r3 = (sg * 4 + 3) * 16;
#pragma unroll
            for (int k4 = 0; k4 < 16; k4++) {
                float4 t0 = tsh4[r0 + k4];
                float4 t1 = tsh4[r1 + k4];
                float4 t2 = tsh4[r2 + k4];
                float4 t3 = tsh4[r3 + k4];
                float wa = w2r[4 * k4], wb = w2r[4 * k4 + 1];
                float wc = w2r[4 * k4 + 2], wd = w2r[4 * k4 + 3];
                ac0 = fmaf(t0.x, wa, ac0); ac1 = fmaf(t1.x, wa, ac1);
                ac2 = fmaf(t2.x, wa, ac2); ac3 = fmaf(t3.x, wa, ac3);
                ac0 = fmaf(t0.y, wb, ac0); ac1 = fmaf(t1.y, wb, ac1);
                ac2 = fmaf(t2.y, wb, ac2); ac3 = fmaf(t3.y, wb, ac3);
                ac0 = fmaf(t0.z, wc, ac0); ac1 = fmaf(t1.z, wc, ac1);
                ac2 = fmaf(t2.z, wc, ac2); ac3 = fmaf(t3.z, wc, ac3);
                ac0 = fmaf(t0.w, wd, ac0); ac1 = fmaf(t1.w, wd, ac1);
                ac2 = fmaf(t2.w, wd, ac2); ac3 = fmaf(t3.w, wd, ac3);
            }
        }
        float y0 = fmaxf(ac0, 0.f), y1 = fmaxf(ac1, 0.f);
        float y2 = fmaxf(ac2, 0.f), y3 = fmaxf(ac3, 0.f);
        g_y[(node0 + sg * 4 + 0) * HID + o] = y0;
        g_y[(node0 + sg * 4 + 1) * HID + o] = y1;
        g_y[(node0 + sg * 4 + 2) * HID + o] = y2;
        g_y[(node0 + sg * 4 + 3) * HID + o] = y3;
        ssum += y0 + y1 + y2 + y3;
        ssq  += y0 * y0 + y1 * y1 + y2 * y2 + y3 * y3;
        __syncthreads();
    }
    red[0][tid] = ssum; red[1][tid] = ssq;
    __syncthreads();
    if (tid < HID) {
        atomicAdd(&g_stats[tid],       red[0][tid] + red[0][tid + 64]);
        atomicAdd(&g_stats[HID + tid], red[1][tid] + red[1][tid + 64]);
    }
}

// ---------------- MLP for layer 1 (scalar -> 64 -> 64) ------------------------
__global__ void __launch_bounds__(128, 3) k_mlp1(
    const float* __restrict__ w1a, const float* __restrict__ b1a,
    const float* __restrict__ W2, const float* __restrict__ b2)
{
    __shared__ float zs[MLP_NPB];
    __shared__ float tsh[MLP_NPB * HID];
    __shared__ float red[2][128];

    int tid = threadIdx.x;
    int o = tid & 63, sg = tid >> 6;

    float w2r[HID];
#pragma unroll
    for (int k = 0; k < HID; k++) w2r[k] = W2[k * HID + o];
    float w1o = w1a[o], b1o = b1a[o], b2o = b2[o];

    const float4* tsh4 = (const float4*)tsh;

    float ssum = 0.f, ssq = 0.f;
    const int ngroups = N_NODES / MLP_NPB;
    for (int g = blockIdx.x; g < ngroups; g += gridDim.x) {
        int node0 = g * MLP_NPB;
        if (tid < MLP_NPB) zs[tid] = g_z0[node0 + tid];
        __syncthreads();
        tsh[(sg * 4 + 0) * HID + o] = fmaxf(fmaf(zs[sg * 4 + 0], w1o, b1o), 0.f);
        tsh[(sg * 4 + 1) * HID + o] = fmaxf(fmaf(zs[sg * 4 + 1], w1o, b1o), 0.f);
        tsh[(sg * 4 + 2) * HID + o] = fmaxf(fmaf(zs[sg * 4 + 2], w1o, b1o), 0.f);
        tsh[(sg * 4 + 3) * HID + o] = fmaxf(fmaf(zs[sg * 4 + 3], w1o, b1o), 0.f);
        __syncthreads();

        float ac0 = b2o, ac1 = b2o, ac2 = b2o, ac3 = b2o;
        {
            int r0 = (sg * 4 + 0) * 16, r1 = (sg * 4 + 1) * 16;
            int r2 = (sg * 4 + 2) * 16, r3 = (sg * 4 + 3) * 16;
#pragma unroll
            for (int k4 = 0; k4 < 16; k4++) {
                float4 t0 = tsh4[r0 + k4];
                float4 t1 = tsh4[r1 + k4];
                float4 t2 = tsh4[r2 + k4];
                float4 t3 = tsh4[r3 + k4];
                float wa = w2r[4 * k4], wb = w2r[4 * k4 + 1];
                float wc = w2r[4 * k4 + 2], wd = w2r[4 * k4 + 3];
                ac0 = fmaf(t0.x, wa, ac0); ac1 = fmaf(t1.x, wa, ac1);
                ac2 = fmaf(t2.x, wa, ac2); ac3 = fmaf(t3.x, wa, ac3);
                ac0 = fmaf(t0.y, wb, ac0); ac1 = fmaf(t1.y, wb, ac1);
                ac2 = fmaf(t2.y, wb, ac2); ac3 = fmaf(t3.y, wb, ac3);
                ac0 = fmaf(t0.z, wc, ac0); ac1 = fmaf(t1.z, wc, ac1);
                ac2 = fmaf(t2.z, wc, ac2); ac3 = fmaf(t3.z, wc, ac3);
                ac0 = fmaf(t0.w, wd, ac0); ac1 = fmaf(t1.w, wd, ac1);
                ac2 = fmaf(t2.w, wd, ac2); ac3 = fmaf(t3.w, wd, ac3);
            }
        }
        float y0 = fmaxf(ac0, 0.f), y1 = fmaxf(ac1, 0.f);
        float y2 = fmaxf(ac2, 0.f), y3 = fmaxf(ac3, 0.f);
        g_y[(node0 + sg * 4 + 0) * HID + o] = y0;
        g_y[(node0 + sg * 4 + 1) * HID + o] = y1;
        g_y[(node0 + sg * 4 + 2) * HID + o] = y2;
        g_y[(node0 + sg * 4 + 3) * HID + o] = y3;
        ssum += y0 + y1 + y2 + y3;
        ssq  += y0 * y0 + y1 * y1 + y2 * y2 + y3 * y3;
        __syncthreads();
    }
    red[0][tid] = ssum; red[1][tid] = ssq;
    __syncthreads();
    if (tid < HID) {
        atomicAdd(&g_stats[tid],       red[0][tid] + red[0][tid + 64]);
        atomicAdd(&g_stats[HID + tid], red[1][tid] + red[1][tid + 64]);
    }
}

// ---------------- BN stats -> affine (scale/shift), reset stats ---------------
__global__ void k_bn(const float* __restrict__ gamma, const float* __restrict__ beta) {
    int f = threadIdx.x;
    if (f < HID) {
        float s = g_stats[f], q = g_stats[HID + f];
        const float inv = 1.f / (float)N_NODES;
        float mu = s * inv;
        float var = q * inv - mu * mu;
        float rstd = rsqrtf(var + 1e-5f);
        float sc = gamma[f] * rstd;
        g_scale[f] = sc;
        g_shift[f] = beta[f] - mu * sc;
        g_stats[f] = 0.f;
        g_stats[HID + f] = 0.f;
    }
}

// ---------------- final: out = (y*sc+sh) @ fc_w + fc_b ------------------------
__global__ void k_fc(const float* __restrict__ fcw, const float* __restrict__ fcb,
                     float* __restrict__ out) {
    int gw = (blockIdx.x * blockDim.x + threadIdx.x) >> 5;
    if (gw >= N_NODES) return;
    int lane = threadIdx.x & 31;
    float2 y  = ((const float2*)g_y)[gw * 32 + lane];
    float2 sc = ((const float2*)g_scale)[lane];
    float2 sh = ((const float2*)g_shift)[lane];
    float2 fw = ((const float2*)fcw)[lane];
    float p = fmaf(fmaf(y.x, sc.x, sh.x), fw.x,
                   fmaf(y.y, sc.y, sh.y) * fw.y);
#pragma unroll
    for (int off = 16; off; off >>= 1) p += __shfl_down_sync(FULL, p, off);
    if (lane == 0) out[gw] = p + fcb[0];
}

// ---------------- launch ------------------------------------------------------
extern "C" void kernel_launch(void* const* d_in, const int* in_sizes, int n_in,
                              void* d_out, int out_size) {
    const float* x      = (const float*)d_in[0];
    const int*   ei     = (const int*)  d_in[1];
    const int*   src    = ei;
    const int*   dst    = ei + N_EDGES;
    const float* w1a    = (const float*)d_in[2];
    const float* b1a    = (const float*)d_in[3];
    const float* w2a    = (const float*)d_in[4];
    const float* b2a    = (const float*)d_in[5];
    const float* w1s    = (const float*)d_in[6];
    const float* b1s    = (const float*)d_in[7];
    const float* w2s    = (const float*)d_in[8];
    const float* b2s    = (const float*)d_in[9];
    const float* eps    = (const float*)d_in[10];
    const float* gammas = (const float*)d_in[11];
    const float* betas  = (const float*)d_in[12];
    const float* fcw    = (const float*)d_in[13];
    const float* fcb    = (const float*)d_in[14];
    float* out = (float*)d_out;

    const int EB4 = (N_EDGES / 4 + 255) / 256;     // int4 edge kernels
    const int WB  = (N_NODES * 32 + 255) / 256;    // warp per node
    const int MLP_GRID = 444;                      // 148 SMs x 3 blocks

    // CSR build (every replay; all scratch state re-derived)
    k_zero<<<(N_NODES + 255) / 256, 256>>>();
    k_hist<<<EB4, 256>>>(dst);
    k_scan<<<1, 1024>>>();
    k_permute<<<EB4, 256>>>(src, dst);

    // layer 1 (scalar input)
    k_agg1<<<WB, 256>>>(x, eps);
    k_mlp1<<<MLP_GRID, 128>>>(w1a, b1a, w2a, b2a);
    k_bn<<<1, 64>>>(gammas, betas);

    // layers 2-4
    for (int l = 0; l < 3; l++) {
        k_agg<<<WB, 256>>>(eps, l + 1);
        k_mlp<<<MLP_GRID, 128>>>(w1s + l * HID * HID, b1s + l * HID,
                                 w2s + l * HID * HID, b2s + l * HID);
        k_bn<<<1, 64>>>(gammas + (l + 1) * HID, betas + (l + 1) * HID);
    }

    // final FC with BN folded
    k_fc<<<WB, 256>>>(fcw, fcb, out);
}